// round 8
// baseline (speedup 1.0000x reference)
#include <cuda_runtime.h>
#include <math.h>

#define NF 16384
#define NB 4096
#define EF 262144
#define EB 65536

struct __align__(16) EdgeRec { int src; float tu; float tv; int cell; };

__device__ float g_H[(size_t)NF * 4096];   // 256 MB scratch: H = X @ W_all
__device__ float g_X1[NF * 96];
__device__ float g_X2[NF * 64];
__device__ float g_X3[NF * 64];
__device__ float g_Yb[NF * 64];
__device__ float g_Wt[96 * 4096];
__device__ int   g_cntf[NF], g_offf[NF + 1], g_curf[NF];
__device__ int   g_cntb[NF], g_offb[NF + 1], g_curb[NF];
__device__ EdgeRec g_ef[EF];
__device__ EdgeRec g_eb[EB];

// ---------------- CSR build ----------------
__global__ void resetCnt(int* a, int* b) {
    int id = blockIdx.x * blockDim.x + threadIdx.x;
    if (id < NF) { a[id] = 0; b[id] = 0; }
}

__global__ void histK(const int* __restrict__ tgt, int E, int* __restrict__ cnt) {
    int e = blockIdx.x * blockDim.x + threadIdx.x;
    if (e < E) atomicAdd(&cnt[tgt[e]], 1);
}

__global__ void scan16k(const int* __restrict__ cnt, int* __restrict__ offs,
                        int* __restrict__ cur) {
    __shared__ int s[1024];
    int t = threadIdx.x;
    int base = t * 16;
    int local[16];
    int sum = 0;
#pragma unroll
    for (int j = 0; j < 16; j++) { local[j] = sum; sum += cnt[base + j]; }
    s[t] = sum;
    __syncthreads();
    for (int off = 1; off < 1024; off <<= 1) {
        int v = (t >= off) ? s[t - off] : 0;
        __syncthreads();
        s[t] += v;
        __syncthreads();
    }
    int pre = s[t] - sum;
#pragma unroll
    for (int j = 0; j < 16; j++) {
        int o = pre + local[j];
        offs[base + j] = o;
        cur[base + j]  = o;
    }
    if (t == 1023) offs[NF] = s[1023];
}

// Edge direction EXACTLY as the reference computes it, including signed zeros:
//   fluid:    d = -(fp[src] - fp[tgt]) / support     (negate = 1)
//   boundary: d =  (bp[src] - fp[tgt]) / support     (negate = 0)
// For self-edges the fluid path yields (-0,-0) whose arctan2 is -pi (cell v=0),
// NOT 0 — this routing matters because tent cells select different weights.
__global__ void buildEdges(const int* __restrict__ tgt, const int* __restrict__ src,
                           const float* __restrict__ tp, const float* __restrict__ sp,
                           const float* __restrict__ supPtr, int negate, int E,
                           int* __restrict__ cur, EdgeRec* __restrict__ recs) {
    int e = blockIdx.x * blockDim.x + threadIdx.x;
    if (e >= E) return;
    int t = tgt[e], s = src[e];
    float sup = supPtr[0];
    float bx = sp[2 * s]     - tp[2 * t];      // src - tgt
    float by = sp[2 * s + 1] - tp[2 * t + 1];
    if (negate) { bx = -bx; by = -by; }        // exact IEEE negation: +0 -> -0
    float dx = bx / sup;
    float dy = by / sup;
    dx = fminf(fmaxf(dx, -1.f), 1.f);          // preserves -0
    dy = fminf(fmaxf(dy, -1.f), 1.f);
    float r = sqrtf(dx * dx + dy * dy + 1e-12f);
    float u = 2.f * r - 1.f;                   // radial in [-1,1]
    float theta;
    if (dx == 0.f && dy == 0.f) {
        // explicit IEEE atan2 zero semantics (robust under fast-math approx):
        // atan2(+-0, -0) = +-pi ; atan2(+-0, +0) = +-0
        theta = (__float_as_int(dx) < 0) ? copysignf(3.14159265358979323846f, dy)
                                         : copysignf(0.f, dy);
    } else {
        theta = atan2f(dy, dx);
    }
    float v = theta / 3.14159265358979323846f; // theta / pi in [-1,1]
    EdgeRec rec;
    rec.src  = s;
    rec.tu   = (u + 1.f) * 3.5f;   // tent coordinate, centers at 0..7
    rec.tv   = (v + 1.f) * 3.5f;
    rec.cell = 0;
    int pos = atomicAdd(&cur[t], 1);
    recs[pos] = rec;
}

// ---------------- generic weight transpose: Wt[c*(64*cout)+k*cout+o] = W[k,c,o]
__global__ void transW(const float* __restrict__ W, float* __restrict__ Wt,
                       int cin, int cout, int n) {
    int id = blockIdx.x * blockDim.x + threadIdx.x;
    if (id >= n) return;
    int o = id % cout;
    int rest = id / cout;
    int k = rest & 63;
    int c = rest >> 6;
    Wt[id] = W[(k * cin + c) * cout + o];
}

// ---------------- K=4 GEMM: H[M,N] = X[M,4] @ Wt[4,N] ----------------
__global__ void gemmK4(const float* __restrict__ X, const float* __restrict__ Wt,
                       float* __restrict__ H, int M, int N) {
    int id = blockIdx.x * blockDim.x + threadIdx.x;
    if (id >= M * N) return;
    int i = id / N, n = id - i * N;
    float4 x = *(const float4*)&X[i * 4];
    H[id] = x.x * Wt[n] + x.y * Wt[N + n] + x.z * Wt[2 * N + n] + x.w * Wt[3 * N + n];
}

// X1[:,0:32] = relu(ff @ fc0)
__global__ void lin32(const float* __restrict__ ff, const float* __restrict__ fc0,
                      float* __restrict__ X1) {
    int id = blockIdx.x * blockDim.x + threadIdx.x;
    int i = id >> 5, o = id & 31;
    float4 x = *(const float4*)&ff[i * 4];
    float y = x.x * fc0[o] + x.y * fc0[32 + o] + x.z * fc0[64 + o] + x.w * fc0[96 + o];
    X1[i * 96 + o] = fmaxf(y, 0.f);
}

// generic bias GEMM: Y[i*cout+o] = sum_c X[i,c] * F[c*cout+o]
__global__ void gemmBias(const float* __restrict__ X, const float* __restrict__ F,
                         float* __restrict__ Y, int K, int cout, int total) {
    int id = blockIdx.x * blockDim.x + threadIdx.x;
    if (id >= total) return;
    int i = id / cout, o = id - i * cout;
    const float* x = X + (size_t)i * K;
    float y = 0.f;
#pragma unroll 4
    for (int c = 0; c < K; c++) y += x[c] * F[c * cout + o];
    Y[id] = y;
}

// ---------------- SGEMM: C[M,N]=A[M,K]@B[K,N], M,N%128==0, K%8==0 --------------
__global__ __launch_bounds__(256) void sgemm128(int M, int N, int K,
                                                const float* __restrict__ A,
                                                const float* __restrict__ B,
                                                float* __restrict__ C) {
    __shared__ float As[8][128];
    __shared__ float Bs[8][128];
    int tid = threadIdx.x;
    int bm = blockIdx.y * 128, bn = blockIdx.x * 128;
    int arow = tid & 127, acol = (tid >> 7) << 2;
    int brow = tid >> 5,  bcol = (tid & 31) << 2;
    int ty = tid >> 4, tx = tid & 15;
    float acc[8][8];
#pragma unroll
    for (int i = 0; i < 8; i++)
#pragma unroll
        for (int j = 0; j < 8; j++) acc[i][j] = 0.f;

    const float* Ap = A + (size_t)(bm + arow) * K + acol;
    const float* Bp = B + (size_t)brow * N + bn + bcol;

    for (int k0 = 0; k0 < K; k0 += 8) {
        float4 av = *(const float4*)Ap; Ap += 8;
        float4 bv = *(const float4*)Bp; Bp += (size_t)8 * N;
        As[acol + 0][arow] = av.x;
        As[acol + 1][arow] = av.y;
        As[acol + 2][arow] = av.z;
        As[acol + 3][arow] = av.w;
        *(float4*)&Bs[brow][bcol] = bv;
        __syncthreads();
#pragma unroll
        for (int kk = 0; kk < 8; kk++) {
            float a[8], b[8];
            *(float4*)&a[0] = *(const float4*)&As[kk][ty * 8];
            *(float4*)&a[4] = *(const float4*)&As[kk][ty * 8 + 4];
            *(float4*)&b[0] = *(const float4*)&Bs[kk][tx * 8];
            *(float4*)&b[4] = *(const float4*)&Bs[kk][tx * 8 + 4];
#pragma unroll
            for (int i = 0; i < 8; i++)
#pragma unroll
                for (int j = 0; j < 8; j++) acc[i][j] += a[i] * b[j];
        }
        __syncthreads();
    }
#pragma unroll
    for (int i = 0; i < 8; i++) {
        float* cp = C + (size_t)(bm + ty * 8 + i) * N + bn + tx * 8;
        *(float4*)cp       = make_float4(acc[i][0], acc[i][1], acc[i][2], acc[i][3]);
        *(float4*)(cp + 4) = make_float4(acc[i][4], acc[i][5], acc[i][6], acc[i][7]);
    }
}

// ---------------- ONE generic scatter for ALL conv layers ----------------
template <int COUT>
__global__ __launch_bounds__(256) void scatterGen(const EdgeRec* __restrict__ recs,
                                                  const int* __restrict__ offs,
                                                  const float* __restrict__ H,
                                                  const float* __restrict__ bias,
                                                  const float* __restrict__ resid,
                                                  float* __restrict__ out,
                                                  int ldout, int outOff, int doRelu) {
    constexpr int NO = (COUT + 31) / 32;
    int i = blockIdx.x * 8 + (threadIdx.x >> 5);
    int lane = threadIdx.x & 31;
    if (i >= NF) return;
    float acc[NO];
#pragma unroll
    for (int j = 0; j < NO; j++) acc[j] = 0.f;
    int pe = offs[i + 1];
    for (int p = offs[i]; p < pe; ++p) {
        int4 rv = *(const int4*)&recs[p];
        float tu = __int_as_float(rv.y), tv = __int_as_float(rv.z);
        int iu = min(max((int)tu, 0), 6);
        int iv = min(max((int)tv, 0), 6);
        const float* hb = H + (size_t)rv.x * (64 * COUT);
#pragma unroll
        for (int du = 0; du <= 1; du++) {
            float wu = fmaxf(0.f, 1.f - fabsf(tu - (float)(iu + du)));
#pragma unroll
            for (int dv = 0; dv <= 1; dv++) {
                float w = wu * fmaxf(0.f, 1.f - fabsf(tv - (float)(iv + dv)));
                const float* h = hb + ((iu + du) * 8 + (iv + dv)) * COUT;
#pragma unroll
                for (int j = 0; j < NO; j++) {
                    int o = lane + 32 * j;
                    if (COUT % 32 == 0 || o < COUT) acc[j] += w * h[o];
                }
            }
        }
    }
#pragma unroll
    for (int j = 0; j < NO; j++) {
        int o = lane + 32 * j;
        if (COUT % 32 == 0 || o < COUT) {
            float v = acc[j];
            if (bias)  v += bias[(size_t)i * COUT + o];
            if (resid) v += resid[(size_t)i * COUT + o];
            if (doRelu) v = fmaxf(v, 0.f);
            out[(size_t)i * ldout + outOff + o] = v;
        }
    }
}

// ---------------- launch ----------------
extern "C" void kernel_launch(void* const* d_in, const int* in_sizes, int n_in,
                              void* d_out, int out_size) {
    const float* fp    = (const float*)d_in[0];
    const float* bp    = (const float*)d_in[1];
    const float* ff    = (const float*)d_in[2];
    const float* bfeat = (const float*)d_in[3];
    const float* sup   = (const float*)d_in[4];
    const int*   fi    = (const int*)d_in[5];
    const int*   fj    = (const int*)d_in[6];
    const int*   bfm   = (const int*)d_in[7];
    const int*   bb    = (const int*)d_in[8];
    const float* W0    = (const float*)d_in[9];
    const float* W1    = (const float*)d_in[10];
    const float* W2    = (const float*)d_in[11];
    const float* W3    = (const float*)d_in[12];
    const float* W4    = (const float*)d_in[13];
    const float* fc0   = (const float*)d_in[14];
    const float* fc1   = (const float*)d_in[15];
    const float* fc2   = (const float*)d_in[16];
    const float* fc3   = (const float*)d_in[17];
    float* out = (float*)d_out;

    float *H, *X1, *X2, *X3, *Yb, *Wt;
    int *cntf, *offf, *curf, *cntb, *offb, *curb;
    EdgeRec *ef, *eb;
    cudaGetSymbolAddress((void**)&H,  g_H);
    cudaGetSymbolAddress((void**)&X1, g_X1);
    cudaGetSymbolAddress((void**)&X2, g_X2);
    cudaGetSymbolAddress((void**)&X3, g_X3);
    cudaGetSymbolAddress((void**)&Yb, g_Yb);
    cudaGetSymbolAddress((void**)&Wt, g_Wt);
    cudaGetSymbolAddress((void**)&cntf, g_cntf);
    cudaGetSymbolAddress((void**)&offf, g_offf);
    cudaGetSymbolAddress((void**)&curf, g_curf);
    cudaGetSymbolAddress((void**)&cntb, g_cntb);
    cudaGetSymbolAddress((void**)&offb, g_offb);
    cudaGetSymbolAddress((void**)&curb, g_curb);
    cudaGetSymbolAddress((void**)&ef, g_ef);
    cudaGetSymbolAddress((void**)&eb, g_eb);
    float* Hb = H + (size_t)NF * 2048;   // boundary-layer H region

    // CSR build (by target)
    resetCnt<<<64, 256>>>(cntf, cntb);
    histK<<<EF / 256, 256>>>(fi, EF, cntf);
    histK<<<EB / 256, 256>>>(bfm, EB, cntb);
    scan16k<<<1, 1024>>>(cntf, offf, curf);
    scan16k<<<1, 1024>>>(cntb, offb, curb);
    buildEdges<<<EF / 256, 256>>>(fi, fj, fp, fp, sup, 1, EF, curf, ef);
    buildEdges<<<EB / 256, 256>>>(bfm, bb, fp, bp, sup, 0, EB, curb, eb);

    // ---- layer 1: X1 = [relu(ff@fc0) | relu(conv W0) | relu(conv W1)] ----
    lin32<<<NF * 32 / 256, 256>>>(ff, fc0, X1);
    transW<<<(4 * 64 * 32) / 256, 256>>>(W0, Wt, 4, 32, 4 * 64 * 32);
    gemmK4<<<(NF * 2048) / 256, 256>>>(ff, Wt, H, NF, 2048);
    scatterGen<32><<<NF / 8, 256>>>(ef, offf, H, (const float*)0, (const float*)0,
                                    X1, 96, 32, 1);
    transW<<<(4 * 64 * 32) / 256, 256>>>(W1, Wt, 4, 32, 4 * 64 * 32);
    gemmK4<<<(NB * 2048) / 256, 256>>>(bfeat, Wt, Hb, NB, 2048);
    scatterGen<32><<<NF / 8, 256>>>(eb, offb, Hb, (const float*)0, (const float*)0,
                                    X1, 96, 64, 1);

    // ---- layer 2: X2 = relu(conv(X1,W2) + X1@fc1) ----
    transW<<<(96 * 4096) / 256, 256>>>(W2, Wt, 96, 64, 96 * 4096);
    sgemm128<<<dim3(32, 128), 256>>>(NF, 4096, 96, X1, Wt, H);
    gemmBias<<<(NF * 64) / 256, 256>>>(X1, fc1, Yb, 96, 64, NF * 64);
    scatterGen<64><<<NF / 8, 256>>>(ef, offf, H, Yb, (const float*)0, X2, 64, 0, 1);

    // ---- layer 3: X3 = relu(conv(X2,W3) + X2@fc2 + X2) ----
    transW<<<(64 * 4096) / 256, 256>>>(W3, Wt, 64, 64, 64 * 4096);
    sgemm128<<<dim3(32, 128), 256>>>(NF, 4096, 64, X2, Wt, H);
    gemmBias<<<(NF * 64) / 256, 256>>>(X2, fc2, Yb, 64, 64, NF * 64);
    scatterGen<64><<<NF / 8, 256>>>(ef, offf, H, Yb, X2, X3, 64, 0, 1);

    // ---- layer 4: out = conv(X3,W4) + X3@fc3 (no relu) ----
    transW<<<(64 * 64 * 2) / 256, 256>>>(W4, Wt, 64, 2, 64 * 64 * 2);
    sgemm128<<<dim3(1, 128), 256>>>(NF, 128, 64, X3, Wt, H);
    gemmBias<<<(NF * 2) / 256, 256>>>(X3, fc3, Yb, 64, 2, NF * 2);
    scatterGen<2><<<NF / 8, 256>>>(ef, offf, H, Yb, (const float*)0, out, 2, 0, 0);

    (void)in_sizes; (void)n_in; (void)out_size;
}

// round 9
// speedup vs baseline: 1.1991x; 1.1991x over previous
#include <cuda_runtime.h>
#include <math.h>

#define NF 16384
#define NB 4096
#define EF 262144
#define EB 65536

struct __align__(16) EdgeRec { int src; float tu; float tv; int cell; };

__device__ float g_H[(size_t)NF * 4096];   // 256 MB scratch: H = X @ W_all
__device__ float g_X1[NF * 96];
__device__ float g_X2[NF * 64];
__device__ float g_X3[NF * 64];
__device__ float g_Yb[NF * 64];
__device__ float g_Wt[96 * 4096];
__device__ int   g_cntf[NF], g_offf[NF + 1], g_curf[NF];
__device__ int   g_cntb[NF], g_offb[NF + 1], g_curb[NF];
__device__ EdgeRec g_ef[EF];
__device__ EdgeRec g_eb[EB];

// ---------------- CSR build ----------------
__global__ void resetCnt(int* a, int* b) {
    int id = blockIdx.x * blockDim.x + threadIdx.x;
    if (id < NF) { a[id] = 0; b[id] = 0; }
}

__global__ void histK(const int* __restrict__ tgt, int E, int* __restrict__ cnt) {
    int e = blockIdx.x * blockDim.x + threadIdx.x;
    if (e < E) atomicAdd(&cnt[tgt[e]], 1);
}

// single block, 1024 threads, 16 values/thread; warp-shuffle scan (2 syncs total)
__global__ void scan16k(const int* __restrict__ cnt, int* __restrict__ offs,
                        int* __restrict__ cur) {
    __shared__ int wsum[32];
    int t = threadIdx.x;
    int lane = t & 31, warp = t >> 5;
    int base = t * 16;
    int local[16];
    int sum = 0;
#pragma unroll
    for (int j = 0; j < 16; j++) { local[j] = sum; sum += cnt[base + j]; }
    // inclusive warp scan of per-thread sums
    int inc = sum;
#pragma unroll
    for (int o = 1; o < 32; o <<= 1) {
        int v = __shfl_up_sync(0xffffffffu, inc, o);
        if (lane >= o) inc += v;
    }
    if (lane == 31) wsum[warp] = inc;
    __syncthreads();
    if (warp == 0) {
        int w = wsum[lane];
#pragma unroll
        for (int o = 1; o < 32; o <<= 1) {
            int v = __shfl_up_sync(0xffffffffu, w, o);
            if (lane >= o) w += v;
        }
        wsum[lane] = w;   // inclusive scan of warp sums
    }
    __syncthreads();
    int pre = inc - sum + (warp ? wsum[warp - 1] : 0);   // exclusive thread offset
#pragma unroll
    for (int j = 0; j < 16; j++) {
        int o = pre + local[j];
        offs[base + j] = o;
        cur[base + j]  = o;
    }
    if (t == 1023) offs[NF] = pre + sum;
}

// Edge direction EXACTLY as the reference computes it, including signed zeros:
//   fluid:    d = -(fp[src] - fp[tgt]) / support     (negate = 1)
//   boundary: d =  (bp[src] - fp[tgt]) / support     (negate = 0)
// Self-edges on the fluid path give (-0,-0): arctan2(-0,-0) = -pi (cell v=0).
__global__ void buildEdges(const int* __restrict__ tgt, const int* __restrict__ src,
                           const float* __restrict__ tp, const float* __restrict__ sp,
                           const float* __restrict__ supPtr, int negate, int E,
                           int* __restrict__ cur, EdgeRec* __restrict__ recs) {
    int e = blockIdx.x * blockDim.x + threadIdx.x;
    if (e >= E) return;
    int t = tgt[e], s = src[e];
    float sup = supPtr[0];
    float bx = sp[2 * s]     - tp[2 * t];      // src - tgt
    float by = sp[2 * s + 1] - tp[2 * t + 1];
    if (negate) { bx = -bx; by = -by; }        // exact IEEE negation: +0 -> -0
    float dx = bx / sup;
    float dy = by / sup;
    dx = fminf(fmaxf(dx, -1.f), 1.f);          // preserves -0
    dy = fminf(fmaxf(dy, -1.f), 1.f);
    float r = sqrtf(dx * dx + dy * dy + 1e-12f);
    float u = 2.f * r - 1.f;
    float theta;
    if (dx == 0.f && dy == 0.f) {
        theta = (__float_as_int(dx) < 0) ? copysignf(3.14159265358979323846f, dy)
                                         : copysignf(0.f, dy);
    } else {
        theta = atan2f(dy, dx);
    }
    float v = theta / 3.14159265358979323846f;
    EdgeRec rec;
    rec.src  = s;
    rec.tu   = (u + 1.f) * 3.5f;
    rec.tv   = (v + 1.f) * 3.5f;
    rec.cell = 0;
    int pos = atomicAdd(&cur[t], 1);
    recs[pos] = rec;
}

// ---------------- generic weight transpose: Wt[c*(64*cout)+k*cout+o] = W[k,c,o]
__global__ void transW(const float* __restrict__ W, float* __restrict__ Wt,
                       int cin, int cout, int n) {
    int id = blockIdx.x * blockDim.x + threadIdx.x;
    if (id >= n) return;
    int o = id % cout;
    int rest = id / cout;
    int k = rest & 63;
    int c = rest >> 6;
    Wt[id] = W[(k * cin + c) * cout + o];
}

// ---------------- layer-1 conv: cin=4, cout=32, weights in smem --------------
// warp per target node; lane = output channel. Same tent math as scatter.
// If xt != null also writes dst[i*96 + 0:32] = relu(xt[i]@fc0).
__global__ __launch_bounds__(256) void conv4(const EdgeRec* __restrict__ recs,
                                             const int* __restrict__ offs,
                                             const float* __restrict__ xsrc,
                                             const float* __restrict__ W,   // [64][4][32]
                                             const float* __restrict__ xt,
                                             const float* __restrict__ fc0,
                                             float* __restrict__ dst, int dstOff) {
    __shared__ float Ws[8192];
    __shared__ float F0[128];
    for (int t = threadIdx.x; t < 8192; t += 256) Ws[t] = W[t];
    if (xt && threadIdx.x < 128) F0[threadIdx.x] = fc0[threadIdx.x];
    __syncthreads();
    int i = blockIdx.x * 8 + (threadIdx.x >> 5);
    int lane = threadIdx.x & 31;
    if (i >= NF) return;
    float y = 0.f;
    int pe = offs[i + 1];
    for (int p = offs[i]; p < pe; ++p) {
        int4 rv = *(const int4*)&recs[p];
        float tu = __int_as_float(rv.y), tv = __int_as_float(rv.z);
        int iu = min(max((int)tu, 0), 6);
        int iv = min(max((int)tv, 0), 6);
        float4 x = *(const float4*)&xsrc[rv.x * 4];
#pragma unroll
        for (int du = 0; du <= 1; du++) {
            float wu = fmaxf(0.f, 1.f - fabsf(tu - (float)(iu + du)));
#pragma unroll
            for (int dv = 0; dv <= 1; dv++) {
                float w = wu * fmaxf(0.f, 1.f - fabsf(tv - (float)(iv + dv)));
                const float* ws = &Ws[((iu + du) * 8 + (iv + dv)) * 128];
                y += w * (x.x * ws[lane] + x.y * ws[32 + lane]
                        + x.z * ws[64 + lane] + x.w * ws[96 + lane]);
            }
        }
    }
    dst[i * 96 + dstOff + lane] = fmaxf(y, 0.f);
    if (xt) {
        float4 x = *(const float4*)&xt[i * 4];
        float yl = x.x * F0[lane] + x.y * F0[32 + lane]
                 + x.z * F0[64 + lane] + x.w * F0[96 + lane];
        dst[i * 96 + lane] = fmaxf(yl, 0.f);
    }
}

// generic bias GEMM (layer-4 only): Y[i*cout+o] = sum_c X[i,c]*F[c*cout+o]
__global__ void gemmBias(const float* __restrict__ X, const float* __restrict__ F,
                         float* __restrict__ Y, int K, int cout, int total) {
    int id = blockIdx.x * blockDim.x + threadIdx.x;
    if (id >= total) return;
    int i = id / cout, o = id - i * cout;
    const float* x = X + (size_t)i * K;
    float y = 0.f;
#pragma unroll 4
    for (int c = 0; c < K; c++) y += x[c] * F[c * cout + o];
    Y[id] = y;
}

// ---------------- SGEMM, double-buffered: C[M,N]=A[M,K]@B[K,N] -----------------
__global__ __launch_bounds__(256) void sgemm128(int M, int N, int K,
                                                const float* __restrict__ A,
                                                const float* __restrict__ B,
                                                float* __restrict__ C) {
    __shared__ float As[2][8][128];
    __shared__ float Bs[2][8][128];
    int tid = threadIdx.x;
    int bm = blockIdx.y * 128, bn = blockIdx.x * 128;
    int arow = tid & 127, acol = (tid >> 7) << 2;
    int brow = tid >> 5,  bcol = (tid & 31) << 2;
    int ty = tid >> 4, tx = tid & 15;
    float acc[8][8];
#pragma unroll
    for (int i = 0; i < 8; i++)
#pragma unroll
        for (int j = 0; j < 8; j++) acc[i][j] = 0.f;

    const float* Ap = A + (size_t)(bm + arow) * K + acol;
    const float* Bp = B + (size_t)brow * N + bn + bcol;

    // prologue: stage 0
    {
        float4 av = *(const float4*)Ap; Ap += 8;
        float4 bv = *(const float4*)Bp; Bp += (size_t)8 * N;
        As[0][acol + 0][arow] = av.x;
        As[0][acol + 1][arow] = av.y;
        As[0][acol + 2][arow] = av.z;
        As[0][acol + 3][arow] = av.w;
        *(float4*)&Bs[0][brow][bcol] = bv;
    }
    __syncthreads();

    int buf = 0;
    for (int k0 = 8; k0 <= K; k0 += 8) {
        float4 av, bv;
        bool more = k0 < K;
        if (more) {
            av = *(const float4*)Ap; Ap += 8;
            bv = *(const float4*)Bp; Bp += (size_t)8 * N;
        }
#pragma unroll
        for (int kk = 0; kk < 8; kk++) {
            float a[8], b[8];
            *(float4*)&a[0] = *(const float4*)&As[buf][kk][ty * 8];
            *(float4*)&a[4] = *(const float4*)&As[buf][kk][ty * 8 + 4];
            *(float4*)&b[0] = *(const float4*)&Bs[buf][kk][tx * 8];
            *(float4*)&b[4] = *(const float4*)&Bs[buf][kk][tx * 8 + 4];
#pragma unroll
            for (int i = 0; i < 8; i++)
#pragma unroll
                for (int j = 0; j < 8; j++) acc[i][j] += a[i] * b[j];
        }
        if (more) {
            int nb = buf ^ 1;
            As[nb][acol + 0][arow] = av.x;
            As[nb][acol + 1][arow] = av.y;
            As[nb][acol + 2][arow] = av.z;
            As[nb][acol + 3][arow] = av.w;
            *(float4*)&Bs[nb][brow][bcol] = bv;
        }
        __syncthreads();
        buf ^= 1;
    }
#pragma unroll
    for (int i = 0; i < 8; i++) {
        float* cp = C + (size_t)(bm + ty * 8 + i) * N + bn + tx * 8;
        *(float4*)cp       = make_float4(acc[i][0], acc[i][1], acc[i][2], acc[i][3]);
        *(float4*)(cp + 4) = make_float4(acc[i][4], acc[i][5], acc[i][6], acc[i][7]);
    }
}

// ---------------- scatter for COUT=64 with FUSED bias GEMM --------------------
// out[i,:] = relu( conv_scatter + X_b[i,:]@F (+resid) ); F: [KB,64] in smem.
__global__ __launch_bounds__(256) void scatter64F(const EdgeRec* __restrict__ recs,
                                                  const int* __restrict__ offs,
                                                  const float* __restrict__ H,
                                                  const float* __restrict__ Xb,
                                                  const float* __restrict__ F, int KB,
                                                  const float* __restrict__ resid,
                                                  float* __restrict__ out) {
    __shared__ float Fs[96 * 64];
    for (int t = threadIdx.x; t < KB * 64; t += 256) Fs[t] = F[t];
    __syncthreads();
    int i = blockIdx.x * 8 + (threadIdx.x >> 5);
    int lane = threadIdx.x & 31;
    if (i >= NF) return;
    float y0 = 0.f, y1 = 0.f;
    int pe = offs[i + 1];
#pragma unroll 2
    for (int p = offs[i]; p < pe; ++p) {
        int4 rv = *(const int4*)&recs[p];
        float tu = __int_as_float(rv.y), tv = __int_as_float(rv.z);
        int iu = min(max((int)tu, 0), 6);
        int iv = min(max((int)tv, 0), 6);
        const float* hb = H + (size_t)rv.x * 4096;
#pragma unroll
        for (int du = 0; du <= 1; du++) {
            float wu = fmaxf(0.f, 1.f - fabsf(tu - (float)(iu + du)));
#pragma unroll
            for (int dv = 0; dv <= 1; dv++) {
                float w = wu * fmaxf(0.f, 1.f - fabsf(tv - (float)(iv + dv)));
                const float* h = hb + ((iu + du) * 8 + (iv + dv)) * 64;
                y0 += w * h[lane];
                y1 += w * h[lane + 32];
            }
        }
    }
    // fused bias: X_b[i,:] @ F
    const float* x = Xb + (size_t)i * KB;
    for (int c = 0; c < KB; c++) {
        float xv = x[c];
        y0 += xv * Fs[c * 64 + lane];
        y1 += xv * Fs[c * 64 + lane + 32];
    }
    if (resid) { y0 += resid[i * 64 + lane]; y1 += resid[i * 64 + lane + 32]; }
    out[i * 64 + lane]      = fmaxf(y0, 0.f);
    out[i * 64 + lane + 32] = fmaxf(y1, 0.f);
}

// ---------------- scatter for COUT=2 (layer 4), precomputed bias, no relu ------
__global__ __launch_bounds__(256) void scatter2(const EdgeRec* __restrict__ recs,
                                                const int* __restrict__ offs,
                                                const float* __restrict__ H,
                                                const float* __restrict__ bias,
                                                float* __restrict__ out) {
    int i = blockIdx.x * 8 + (threadIdx.x >> 5);
    int lane = threadIdx.x & 31;
    if (i >= NF) return;
    float y0 = 0.f, y1 = 0.f;
    int pe = offs[i + 1];
    for (int p = offs[i] + lane; p < pe; p += 32) {
        int4 rv = *(const int4*)&recs[p];
        float tu = __int_as_float(rv.y), tv = __int_as_float(rv.z);
        int iu = min(max((int)tu, 0), 6);
        int iv = min(max((int)tv, 0), 6);
        const float* hb = H + (size_t)rv.x * 128;
#pragma unroll
        for (int du = 0; du <= 1; du++) {
            float wu = fmaxf(0.f, 1.f - fabsf(tu - (float)(iu + du)));
#pragma unroll
            for (int dv = 0; dv <= 1; dv++) {
                float w = wu * fmaxf(0.f, 1.f - fabsf(tv - (float)(iv + dv)));
                const float* h = hb + ((iu + du) * 8 + (iv + dv)) * 2;
                y0 += w * h[0];
                y1 += w * h[1];
            }
        }
    }
#pragma unroll
    for (int o = 16; o > 0; o >>= 1) {
        y0 += __shfl_xor_sync(0xffffffffu, y0, o);
        y1 += __shfl_xor_sync(0xffffffffu, y1, o);
    }
    if (lane == 0) {
        out[i * 2]     = y0 + bias[i * 2];
        out[i * 2 + 1] = y1 + bias[i * 2 + 1];
    }
}

// ---------------- launch ----------------
extern "C" void kernel_launch(void* const* d_in, const int* in_sizes, int n_in,
                              void* d_out, int out_size) {
    const float* fp    = (const float*)d_in[0];
    const float* bp    = (const float*)d_in[1];
    const float* ff    = (const float*)d_in[2];
    const float* bfeat = (const float*)d_in[3];
    const float* sup   = (const float*)d_in[4];
    const int*   fi    = (const int*)d_in[5];
    const int*   fj    = (const int*)d_in[6];
    const int*   bfm   = (const int*)d_in[7];
    const int*   bb    = (const int*)d_in[8];
    const float* W0    = (const float*)d_in[9];
    const float* W1    = (const float*)d_in[10];
    const float* W2    = (const float*)d_in[11];
    const float* W3    = (const float*)d_in[12];
    const float* W4    = (const float*)d_in[13];
    const float* fc0   = (const float*)d_in[14];
    const float* fc1   = (const float*)d_in[15];
    const float* fc2   = (const float*)d_in[16];
    const float* fc3   = (const float*)d_in[17];
    float* out = (float*)d_out;

    float *H, *X1, *X2, *X3, *Yb, *Wt;
    int *cntf, *offf, *curf, *cntb, *offb, *curb;
    EdgeRec *ef, *eb;
    cudaGetSymbolAddress((void**)&H,  g_H);
    cudaGetSymbolAddress((void**)&X1, g_X1);
    cudaGetSymbolAddress((void**)&X2, g_X2);
    cudaGetSymbolAddress((void**)&X3, g_X3);
    cudaGetSymbolAddress((void**)&Yb, g_Yb);
    cudaGetSymbolAddress((void**)&Wt, g_Wt);
    cudaGetSymbolAddress((void**)&cntf, g_cntf);
    cudaGetSymbolAddress((void**)&offf, g_offf);
    cudaGetSymbolAddress((void**)&curf, g_curf);
    cudaGetSymbolAddress((void**)&cntb, g_cntb);
    cudaGetSymbolAddress((void**)&offb, g_offb);
    cudaGetSymbolAddress((void**)&curb, g_curb);
    cudaGetSymbolAddress((void**)&ef, g_ef);
    cudaGetSymbolAddress((void**)&eb, g_eb);

    // CSR build (by target)
    resetCnt<<<64, 256>>>(cntf, cntb);
    histK<<<EF / 256, 256>>>(fi, EF, cntf);
    histK<<<EB / 256, 256>>>(bfm, EB, cntb);
    scan16k<<<1, 1024>>>(cntf, offf, curf);
    scan16k<<<1, 1024>>>(cntb, offb, curb);
    buildEdges<<<EF / 256, 256>>>(fi, fj, fp, fp, sup, 1, EF, curf, ef);
    buildEdges<<<EB / 256, 256>>>(bfm, bb, fp, bp, sup, 0, EB, curb, eb);

    // ---- layer 1: X1 = [relu(ff@fc0) | relu(conv W0) | relu(conv W1)] ----
    conv4<<<NF / 8, 256>>>(ef, offf, ff,    W0, ff,            fc0,           X1, 32);
    conv4<<<NF / 8, 256>>>(eb, offb, bfeat, W1, (const float*)0, (const float*)0, X1, 64);

    // ---- layer 2: X2 = relu(conv(X1,W2) + X1@fc1) ----
    transW<<<(96 * 4096) / 256, 256>>>(W2, Wt, 96, 64, 96 * 4096);
    sgemm128<<<dim3(32, 128), 256>>>(NF, 4096, 96, X1, Wt, H);
    scatter64F<<<NF / 8, 256>>>(ef, offf, H, X1, fc1, 96, (const float*)0, X2);

    // ---- layer 3: X3 = relu(conv(X2,W3) + X2@fc2 + X2) ----
    transW<<<(64 * 4096) / 256, 256>>>(W3, Wt, 64, 64, 64 * 4096);
    sgemm128<<<dim3(32, 128), 256>>>(NF, 4096, 64, X2, Wt, H);
    scatter64F<<<NF / 8, 256>>>(ef, offf, H, X2, fc2, 64, X2, X3);

    // ---- layer 4: out = conv(X3,W4) + X3@fc3 (no relu) ----
    transW<<<(64 * 64 * 2) / 256, 256>>>(W4, Wt, 64, 2, 64 * 64 * 2);
    sgemm128<<<dim3(1, 128), 256>>>(NF, 128, 64, X3, Wt, H);
    gemmBias<<<(NF * 2) / 256, 256>>>(X3, fc3, Yb, 64, 2, NF * 2);
    scatter2<<<NF / 8, 256>>>(ef, offf, H, Yb, out);

    (void)in_sizes; (void)n_in; (void)out_size;
}

// round 10
// speedup vs baseline: 1.2995x; 1.0837x over previous
#include <cuda_runtime.h>
#include <math.h>

#define NF 16384
#define NB 4096
#define EF 262144
#define EB 65536

struct __align__(16) EdgeRec { int src; float tu; float tv; int cell; };

__device__ float g_H[(size_t)NF * 4096];   // 256 MB scratch: H = X @ W_all
__device__ float g_X1[NF * 96];
__device__ float g_X2[NF * 64];
__device__ float g_X3[NF * 64];
__device__ float g_Yb[NF * 64];
__device__ float g_Wt[96 * 4096];
__device__ int   g_cntf[NF], g_offf[NF + 1], g_curf[NF];
__device__ int   g_cntb[NF], g_offb[NF + 1], g_curb[NF];
__device__ EdgeRec g_ef[EF];
__device__ EdgeRec g_eb[EB];

__device__ __forceinline__ float tf32r(float x) {
    float y;
    asm("cvt.rna.tf32.f32 %0, %1;" : "=f"(y) : "f"(x));
    return y;
}

// ---------------- CSR build ----------------
__global__ void resetCnt(int* a, int* b) {
    int id = blockIdx.x * blockDim.x + threadIdx.x;
    if (id < NF) { a[id] = 0; b[id] = 0; }
}

// fluid + boundary histograms in ONE launch
__global__ void histAll(const int* __restrict__ fi, const int* __restrict__ bfm,
                        int* __restrict__ cf, int* __restrict__ cb) {
    int e = blockIdx.x * blockDim.x + threadIdx.x;
    if (e < EF) atomicAdd(&cf[fi[e]], 1);
    else if (e < EF + EB) atomicAdd(&cb[bfm[e - EF]], 1);
}

// both scans in ONE launch: block 0 -> fluid, block 1 -> boundary
__global__ void scan2(const int* __restrict__ cf, int* __restrict__ of, int* __restrict__ uf,
                      const int* __restrict__ cb, int* __restrict__ ob, int* __restrict__ ub) {
    const int* cnt = blockIdx.x ? cb : cf;
    int* offs = blockIdx.x ? ob : of;
    int* cur  = blockIdx.x ? ub : uf;
    __shared__ int wsum[32];
    int t = threadIdx.x;
    int lane = t & 31, warp = t >> 5;
    int base = t * 16;
    int local[16];
    int sum = 0;
#pragma unroll
    for (int j = 0; j < 16; j++) { local[j] = sum; sum += cnt[base + j]; }
    int inc = sum;
#pragma unroll
    for (int o = 1; o < 32; o <<= 1) {
        int v = __shfl_up_sync(0xffffffffu, inc, o);
        if (lane >= o) inc += v;
    }
    if (lane == 31) wsum[warp] = inc;
    __syncthreads();
    if (warp == 0) {
        int w = wsum[lane];
#pragma unroll
        for (int o = 1; o < 32; o <<= 1) {
            int v = __shfl_up_sync(0xffffffffu, w, o);
            if (lane >= o) w += v;
        }
        wsum[lane] = w;
    }
    __syncthreads();
    int pre = inc - sum + (warp ? wsum[warp - 1] : 0);
#pragma unroll
    for (int j = 0; j < 16; j++) {
        int o = pre + local[j];
        offs[base + j] = o;
        cur[base + j]  = o;
    }
    if (t == 1023) offs[NF] = pre + sum;
}

// Edge direction EXACTLY as the reference computes it, including signed zeros:
//   fluid:    d = -(fp[src] - fp[tgt]) / support
//   boundary: d =  (bp[src] - fp[tgt]) / support
// Self-edges on the fluid path give (-0,-0): arctan2(-0,-0) = -pi (cell v=0).
// Both edge sets in ONE launch; core math byte-identical to the verified version.
__global__ void buildAll(const int* __restrict__ fi, const int* __restrict__ fj,
                         const int* __restrict__ bfm, const int* __restrict__ bb,
                         const float* __restrict__ fp, const float* __restrict__ bp,
                         const float* __restrict__ supPtr,
                         int* __restrict__ curf, EdgeRec* __restrict__ ef,
                         int* __restrict__ curb, EdgeRec* __restrict__ eb) {
    int e = blockIdx.x * blockDim.x + threadIdx.x;
    if (e >= EF + EB) return;
    int t, s, negate;
    const float *tp, *sp;
    int* cur;
    EdgeRec* recs;
    if (e < EF) {
        t = fi[e]; s = fj[e]; tp = fp; sp = fp; negate = 1; cur = curf; recs = ef;
    } else {
        int eb2 = e - EF;
        t = bfm[eb2]; s = bb[eb2]; tp = fp; sp = bp; negate = 0; cur = curb; recs = eb;
    }
    float sup = supPtr[0];
    float bx = sp[2 * s]     - tp[2 * t];      // src - tgt
    float by = sp[2 * s + 1] - tp[2 * t + 1];
    if (negate) { bx = -bx; by = -by; }        // exact IEEE negation: +0 -> -0
    float dx = bx / sup;
    float dy = by / sup;
    dx = fminf(fmaxf(dx, -1.f), 1.f);
    dy = fminf(fmaxf(dy, -1.f), 1.f);
    float r = sqrtf(dx * dx + dy * dy + 1e-12f);
    float u = 2.f * r - 1.f;
    float theta;
    if (dx == 0.f && dy == 0.f) {
        theta = (__float_as_int(dx) < 0) ? copysignf(3.14159265358979323846f, dy)
                                         : copysignf(0.f, dy);
    } else {
        theta = atan2f(dy, dx);
    }
    float v = theta / 3.14159265358979323846f;
    EdgeRec rec;
    rec.src  = s;
    rec.tu   = (u + 1.f) * 3.5f;
    rec.tv   = (v + 1.f) * 3.5f;
    rec.cell = 0;
    int pos = atomicAdd(&cur[t], 1);
    recs[pos] = rec;
}

// ---------------- generic weight transpose: Wt[c*(64*cout)+k*cout+o] = W[k,c,o]
__global__ void transW(const float* __restrict__ W, float* __restrict__ Wt,
                       int cin, int cout, int n) {
    int id = blockIdx.x * blockDim.x + threadIdx.x;
    if (id >= n) return;
    int o = id % cout;
    int rest = id / cout;
    int k = rest & 63;
    int c = rest >> 6;
    Wt[id] = W[(k * cin + c) * cout + o];
}

// ---------------- layer-1 conv: cin=4, cout=32, weights in smem --------------
__global__ __launch_bounds__(256) void conv4(const EdgeRec* __restrict__ recs,
                                             const int* __restrict__ offs,
                                             const float* __restrict__ xsrc,
                                             const float* __restrict__ W,   // [64][4][32]
                                             const float* __restrict__ xt,
                                             const float* __restrict__ fc0,
                                             float* __restrict__ dst, int dstOff) {
    __shared__ float Ws[8192];
    __shared__ float F0[128];
    for (int t = threadIdx.x; t < 8192; t += 256) Ws[t] = W[t];
    if (xt && threadIdx.x < 128) F0[threadIdx.x] = fc0[threadIdx.x];
    __syncthreads();
    int i = blockIdx.x * 8 + (threadIdx.x >> 5);
    int lane = threadIdx.x & 31;
    if (i >= NF) return;
    float y = 0.f;
    int pe = offs[i + 1];
    for (int p = offs[i]; p < pe; ++p) {
        int4 rv = *(const int4*)&recs[p];
        float tu = __int_as_float(rv.y), tv = __int_as_float(rv.z);
        int iu = min(max((int)tu, 0), 6);
        int iv = min(max((int)tv, 0), 6);
        float4 x = *(const float4*)&xsrc[rv.x * 4];
#pragma unroll
        for (int du = 0; du <= 1; du++) {
            float wu = fmaxf(0.f, 1.f - fabsf(tu - (float)(iu + du)));
#pragma unroll
            for (int dv = 0; dv <= 1; dv++) {
                float w = wu * fmaxf(0.f, 1.f - fabsf(tv - (float)(iv + dv)));
                const float* ws = &Ws[((iu + du) * 8 + (iv + dv)) * 128];
                y += w * (x.x * ws[lane] + x.y * ws[32 + lane]
                        + x.z * ws[64 + lane] + x.w * ws[96 + lane]);
            }
        }
    }
    dst[i * 96 + dstOff + lane] = fmaxf(y, 0.f);
    if (xt) {
        float4 x = *(const float4*)&xt[i * 4];
        float yl = x.x * F0[lane] + x.y * F0[32 + lane]
                 + x.z * F0[64 + lane] + x.w * F0[96 + lane];
        dst[i * 96 + lane] = fmaxf(yl, 0.f);
    }
}

// generic bias GEMM (layer-4 only): Y[i*cout+o] = sum_c X[i,c]*F[c*cout+o]
__global__ void gemmBias(const float* __restrict__ X, const float* __restrict__ F,
                         float* __restrict__ Y, int K, int cout, int total) {
    int id = blockIdx.x * blockDim.x + threadIdx.x;
    if (id >= total) return;
    int i = id / cout, o = id - i * cout;
    const float* x = X + (size_t)i * K;
    float y = 0.f;
#pragma unroll 4
    for (int c = 0; c < K; c++) y += x[c] * F[c * cout + o];
    Y[id] = y;
}

// ---------------- 3xTF32 tensor-core GEMM: C[M,N] = A[M,K] @ B[K,N] ------------
// Block 128x128, 8 warps of 64x32. Operands split hi/lo (tf32); C = AhBh+AlBh+AhBl.
// Requires M%128==0, N%128==0, K%16==0.
__device__ __forceinline__ void mma8(float d[4], const unsigned a[4], const unsigned b[2]) {
    asm volatile("mma.sync.aligned.m16n8k8.row.col.f32.tf32.tf32.f32 "
                 "{%0,%1,%2,%3}, {%4,%5,%6,%7}, {%8,%9}, {%0,%1,%2,%3};"
                 : "+f"(d[0]), "+f"(d[1]), "+f"(d[2]), "+f"(d[3])
                 : "r"(a[0]), "r"(a[1]), "r"(a[2]), "r"(a[3]),
                   "r"(b[0]), "r"(b[1]));
}

#define TGBK 16
#define TGPAD 136
__global__ __launch_bounds__(256) void tf32gemm(int M, int N, int K,
                                                const float* __restrict__ A,
                                                const float* __restrict__ B,
                                                float* __restrict__ C) {
    __shared__ float Ah[TGBK][TGPAD], Al[TGBK][TGPAD];
    __shared__ float Bh[TGBK][TGPAD], Bl[TGBK][TGPAD];
    int tid = threadIdx.x;
    int bm = blockIdx.y * 128, bn = blockIdx.x * 128;
    int w = tid >> 5, lane = tid & 31;
    int wm = (w & 1) * 64, wn = (w >> 1) * 32;
    int r = lane >> 2, c = lane & 3;
    float acc[4][4][4];
#pragma unroll
    for (int mt = 0; mt < 4; mt++)
#pragma unroll
        for (int nt = 0; nt < 4; nt++)
#pragma unroll
            for (int q = 0; q < 4; q++) acc[mt][nt][q] = 0.f;

    int arow = tid >> 1, akq = (tid & 1) * 8;   // A: 128 rows x 16 k
    int bk = tid >> 4,  bnq = (tid & 15) * 8;   // B: 16 k x 128 n

    for (int k0 = 0; k0 < K; k0 += TGBK) {
        // stage A (transposed to [k][m]) with hi/lo split
        {
            const float* ap = A + (size_t)(bm + arow) * K + k0 + akq;
            float4 v0 = *(const float4*)ap;
            float4 v1 = *(const float4*)(ap + 4);
            float v[8] = {v0.x, v0.y, v0.z, v0.w, v1.x, v1.y, v1.z, v1.w};
#pragma unroll
            for (int j = 0; j < 8; j++) {
                float hi = tf32r(v[j]);
                Ah[akq + j][arow] = hi;
                Al[akq + j][arow] = tf32r(v[j] - hi);
            }
        }
        // stage B ([k][n]) with hi/lo split
        {
            const float* bp = B + (size_t)(k0 + bk) * N + bn + bnq;
            float4 v0 = *(const float4*)bp;
            float4 v1 = *(const float4*)(bp + 4);
            float4 h0 = make_float4(tf32r(v0.x), tf32r(v0.y), tf32r(v0.z), tf32r(v0.w));
            float4 h1 = make_float4(tf32r(v1.x), tf32r(v1.y), tf32r(v1.z), tf32r(v1.w));
            float4 l0 = make_float4(tf32r(v0.x - h0.x), tf32r(v0.y - h0.y),
                                    tf32r(v0.z - h0.z), tf32r(v0.w - h0.w));
            float4 l1 = make_float4(tf32r(v1.x - h1.x), tf32r(v1.y - h1.y),
                                    tf32r(v1.z - h1.z), tf32r(v1.w - h1.w));
            *(float4*)&Bh[bk][bnq]     = h0;
            *(float4*)&Bh[bk][bnq + 4] = h1;
            *(float4*)&Bl[bk][bnq]     = l0;
            *(float4*)&Bl[bk][bnq + 4] = l1;
        }
        __syncthreads();

#pragma unroll
        for (int ks = 0; ks < TGBK; ks += 8) {
            unsigned afh[4][4], bfh[4][2];
#pragma unroll
            for (int mt = 0; mt < 4; mt++) {
                int m = wm + mt * 16 + r;
                afh[mt][0] = __float_as_uint(Ah[ks + c][m]);
                afh[mt][1] = __float_as_uint(Ah[ks + c][m + 8]);
                afh[mt][2] = __float_as_uint(Ah[ks + c + 4][m]);
                afh[mt][3] = __float_as_uint(Ah[ks + c + 4][m + 8]);
            }
#pragma unroll
            for (int nt = 0; nt < 4; nt++) {
                int n = wn + nt * 8 + r;
                bfh[nt][0] = __float_as_uint(Bh[ks + c][n]);
                bfh[nt][1] = __float_as_uint(Bh[ks + c + 4][n]);
            }
#pragma unroll
            for (int mt = 0; mt < 4; mt++)
#pragma unroll
                for (int nt = 0; nt < 4; nt++) mma8(acc[mt][nt], afh[mt], bfh[nt]);
            // lo(A) * hi(B)
            {
                unsigned afl[4][4];
#pragma unroll
                for (int mt = 0; mt < 4; mt++) {
                    int m = wm + mt * 16 + r;
                    afl[mt][0] = __float_as_uint(Al[ks + c][m]);
                    afl[mt][1] = __float_as_uint(Al[ks + c][m + 8]);
                    afl[mt][2] = __float_as_uint(Al[ks + c + 4][m]);
                    afl[mt][3] = __float_as_uint(Al[ks + c + 4][m + 8]);
                }
#pragma unroll
                for (int mt = 0; mt < 4; mt++)
#pragma unroll
                    for (int nt = 0; nt < 4; nt++) mma8(acc[mt][nt], afl[mt], bfh[nt]);
            }
            // hi(A) * lo(B)
            {
                unsigned bfl[4][2];
#pragma unroll
                for (int nt = 0; nt < 4; nt++) {
                    int n = wn + nt * 8 + r;
                    bfl[nt][0] = __float_as_uint(Bl[ks + c][n]);
                    bfl[nt][1] = __float_as_uint(Bl[ks + c + 4][n]);
                }
#pragma unroll
                for (int mt = 0; mt < 4; mt++)
#pragma unroll
                    for (int nt = 0; nt < 4; nt++) mma8(acc[mt][nt], afh[mt], bfl[nt]);
            }
        }
        __syncthreads();
    }
#pragma unroll
    for (int mt = 0; mt < 4; mt++)
#pragma unroll
        for (int nt = 0; nt < 4; nt++) {
            int m0 = bm + wm + mt * 16 + r;
            int n0 = bn + wn + nt * 8 + 2 * c;
            float* cp = C + (size_t)m0 * N + n0;
            *(float2*)cp = make_float2(acc[mt][nt][0], acc[mt][nt][1]);
            float* cp2 = C + (size_t)(m0 + 8) * N + n0;
            *(float2*)cp2 = make_float2(acc[mt][nt][2], acc[mt][nt][3]);
        }
}

// ---------------- scatter for COUT=64 with FUSED bias GEMM --------------------
__global__ __launch_bounds__(256) void scatter64F(const EdgeRec* __restrict__ recs,
                                                  const int* __restrict__ offs,
                                                  const float* __restrict__ H,
                                                  const float* __restrict__ Xb,
                                                  const float* __restrict__ F, int KB,
                                                  const float* __restrict__ resid,
                                                  float* __restrict__ out) {
    __shared__ float Fs[96 * 64];
    for (int t = threadIdx.x; t < KB * 64; t += 256) Fs[t] = F[t];
    __syncthreads();
    int i = blockIdx.x * 8 + (threadIdx.x >> 5);
    int lane = threadIdx.x & 31;
    if (i >= NF) return;
    float y0 = 0.f, y1 = 0.f;
    int pe = offs[i + 1];
#pragma unroll 2
    for (int p = offs[i]; p < pe; ++p) {
        int4 rv = *(const int4*)&recs[p];
        float tu = __int_as_float(rv.y), tv = __int_as_float(rv.z);
        int iu = min(max((int)tu, 0), 6);
        int iv = min(max((int)tv, 0), 6);
        const float* hb = H + (size_t)rv.x * 4096;
#pragma unroll
        for (int du = 0; du <= 1; du++) {
            float wu = fmaxf(0.f, 1.f - fabsf(tu - (float)(iu + du)));
#pragma unroll
            for (int dv = 0; dv <= 1; dv++) {
                float w = wu * fmaxf(0.f, 1.f - fabsf(tv - (float)(iv + dv)));
                const float* h = hb + ((iu + du) * 8 + (iv + dv)) * 64;
                y0 += w * h[lane];
                y1 += w * h[lane + 32];
            }
        }
    }
    const float* x = Xb + (size_t)i * KB;
    for (int cc = 0; cc < KB; cc++) {
        float xv = x[cc];
        y0 += xv * Fs[cc * 64 + lane];
        y1 += xv * Fs[cc * 64 + lane + 32];
    }
    if (resid) { y0 += resid[i * 64 + lane]; y1 += resid[i * 64 + lane + 32]; }
    out[i * 64 + lane]      = fmaxf(y0, 0.f);
    out[i * 64 + lane + 32] = fmaxf(y1, 0.f);
}

// ---------------- scatter for COUT=2 (layer 4), precomputed bias, no relu ------
__global__ __launch_bounds__(256) void scatter2(const EdgeRec* __restrict__ recs,
                                                const int* __restrict__ offs,
                                                const float* __restrict__ H,
                                                const float* __restrict__ bias,
                                                float* __restrict__ out) {
    int i = blockIdx.x * 8 + (threadIdx.x >> 5);
    int lane = threadIdx.x & 31;
    if (i >= NF) return;
    float y0 = 0.f, y1 = 0.f;
    int pe = offs[i + 1];
    for (int p = offs[i] + lane; p < pe; p += 32) {
        int4 rv = *(const int4*)&recs[p];
        float tu = __int_as_float(rv.y), tv = __int_as_float(rv.z);
        int iu = min(max((int)tu, 0), 6);
        int iv = min(max((int)tv, 0), 6);
        const float* hb = H + (size_t)rv.x * 128;
#pragma unroll
        for (int du = 0; du <= 1; du++) {
            float wu = fmaxf(0.f, 1.f - fabsf(tu - (float)(iu + du)));
#pragma unroll
            for (int dv = 0; dv <= 1; dv++) {
                float w = wu * fmaxf(0.f, 1.f - fabsf(tv - (float)(iv + dv)));
                const float* h = hb + ((iu + du) * 8 + (iv + dv)) * 2;
                y0 += w * h[0];
                y1 += w * h[1];
            }
        }
    }
#pragma unroll
    for (int o = 16; o > 0; o >>= 1) {
        y0 += __shfl_xor_sync(0xffffffffu, y0, o);
        y1 += __shfl_xor_sync(0xffffffffu, y1, o);
    }
    if (lane == 0) {
        out[i * 2]     = y0 + bias[i * 2];
        out[i * 2 + 1] = y1 + bias[i * 2 + 1];
    }
}

// ---------------- launch ----------------
extern "C" void kernel_launch(void* const* d_in, const int* in_sizes, int n_in,
                              void* d_out, int out_size) {
    const float* fp    = (const float*)d_in[0];
    const float* bp    = (const float*)d_in[1];
    const float* ff    = (const float*)d_in[2];
    const float* bfeat = (const float*)d_in[3];
    const float* sup   = (const float*)d_in[4];
    const int*   fi    = (const int*)d_in[5];
    const int*   fj    = (const int*)d_in[6];
    const int*   bfm   = (const int*)d_in[7];
    const int*   bb    = (const int*)d_in[8];
    const float* W0    = (const float*)d_in[9];
    const float* W1    = (const float*)d_in[10];
    const float* W2    = (const float*)d_in[11];
    const float* W3    = (const float*)d_in[12];
    const float* W4    = (const float*)d_in[13];
    const float* fc0   = (const float*)d_in[14];
    const float* fc1   = (const float*)d_in[15];
    const float* fc2   = (const float*)d_in[16];
    const float* fc3   = (const float*)d_in[17];
    float* out = (float*)d_out;

    float *H, *X1, *X2, *X3, *Yb, *Wt;
    int *cntf, *offf, *curf, *cntb, *offb, *curb;
    EdgeRec *ef, *eb;
    cudaGetSymbolAddress((void**)&H,  g_H);
    cudaGetSymbolAddress((void**)&X1, g_X1);
    cudaGetSymbolAddress((void**)&X2, g_X2);
    cudaGetSymbolAddress((void**)&X3, g_X3);
    cudaGetSymbolAddress((void**)&Yb, g_Yb);
    cudaGetSymbolAddress((void**)&Wt, g_Wt);
    cudaGetSymbolAddress((void**)&cntf, g_cntf);
    cudaGetSymbolAddress((void**)&offf, g_offf);
    cudaGetSymbolAddress((void**)&curf, g_curf);
    cudaGetSymbolAddress((void**)&cntb, g_cntb);
    cudaGetSymbolAddress((void**)&offb, g_offb);
    cudaGetSymbolAddress((void**)&curb, g_curb);
    cudaGetSymbolAddress((void**)&ef, g_ef);
    cudaGetSymbolAddress((void**)&eb, g_eb);

    // CSR build (by target)
    resetCnt<<<64, 256>>>(cntf, cntb);
    histAll<<<(EF + EB) / 256, 256>>>(fi, bfm, cntf, cntb);
    scan2<<<2, 1024>>>(cntf, offf, curf, cntb, offb, curb);
    buildAll<<<(EF + EB) / 256, 256>>>(fi, fj, bfm, bb, fp, bp, sup,
                                       curf, ef, curb, eb);

    // ---- layer 1: X1 = [relu(ff@fc0) | relu(conv W0) | relu(conv W1)] ----
    conv4<<<NF / 8, 256>>>(ef, offf, ff,    W0, ff,              fc0,             X1, 32);
    conv4<<<NF / 8, 256>>>(eb, offb, bfeat, W1, (const float*)0, (const float*)0, X1, 64);

    // ---- layer 2: X2 = relu(conv(X1,W2) + X1@fc1) ----
    transW<<<(96 * 4096) / 256, 256>>>(W2, Wt, 96, 64, 96 * 4096);
    tf32gemm<<<dim3(32, 128), 256>>>(NF, 4096, 96, X1, Wt, H);
    scatter64F<<<NF / 8, 256>>>(ef, offf, H, X1, fc1, 96, (const float*)0, X2);

    // ---- layer 3: X3 = relu(conv(X2,W3) + X2@fc2 + X2) ----
    transW<<<(64 * 4096) / 256, 256>>>(W3, Wt, 64, 64, 64 * 4096);
    tf32gemm<<<dim3(32, 128), 256>>>(NF, 4096, 64, X2, Wt, H);
    scatter64F<<<NF / 8, 256>>>(ef, offf, H, X2, fc2, 64, X2, X3);

    // ---- layer 4: out = conv(X3,W4) + X3@fc3 (no relu) ----
    transW<<<(64 * 64 * 2) / 256, 256>>>(W4, Wt, 64, 2, 64 * 64 * 2);
    tf32gemm<<<dim3(1, 128), 256>>>(NF, 128, 64, X3, Wt, H);
    gemmBias<<<(NF * 2) / 256, 256>>>(X3, fc3, Yb, 64, 2, NF * 2);
    scatter2<<<NF / 8, 256>>>(ef, offf, H, Yb, out);

    (void)in_sizes; (void)n_in; (void)out_size;
}